// round 12
// baseline (speedup 1.0000x reference)
#include <cuda_runtime.h>
#include <cuda_fp16.h>
#include <math.h>

#define NN 50000
#define EE 800000
#define HID 64
#define NH 3
#define D1 192   // NH*HID
#define TN 32    // nodes per k_xs block

// ---------------- scratch (device globals) ----------------
__device__ __half2 g_xs1h[NN*(D1/2)];  // h @ W1_src, fp16 (96 half2 per node)
__device__ float  g_as1[NN*4];     // per-node a_src (3 used, padded to float4)
__device__ float  g_ad1[NN*4];     // per-node a_dst
__device__ int    g_src[EE];
__device__ int    g_dst[EE];
__device__ int    g_deg[NN];
__device__ int    g_rowptr[NN+1];
__device__ int    g_cursor[NN];
__device__ float4 g_er[EE];        // per-edge {w0,w1,w2,src_bits} grouped by dst (w=exp(logit))
__device__ int    g_esrc[EE];      // per-edge src grouped by dst (for k_l2)
__device__ float  g_eea[EE];       // per-edge edge_attr*ce2 grouped by dst
__device__ float2 g_a2sx[NN];      // {a2s, xs2}
__device__ float  g_a2d[NN];       // (h1 @ W2_dst) * att2_dst
__device__ float  g_watt[HID*6];   // [k*6+q]: q<3 -> fold(W1_src,att1_src), q>=3 -> fold(W1_dst,att1_dst)
__device__ float  g_ce1[NH];
__device__ float  g_ce2;
__device__ int    g_is64;

__device__ __forceinline__ float lrelu(float v){ return v > 0.f ? v : 0.2f*v; }

// bit-cast two floats -> packed __half2 -> uint
__device__ __forceinline__ unsigned int f2_to_h2u(float a, float b){
    __half2 h = __floats2half2_rn(a, b);
    union { __half2 h; unsigned int u; } cvt;
    cvt.h = h;
    return cvt.u;
}

// ---------------- front: zero deg + folds + dtype detect ----------------
__global__ void k_front(const float* __restrict__ W1_src, const float* __restrict__ att1_src,
                        const float* __restrict__ W1_dst, const float* __restrict__ att1_dst,
                        const float* __restrict__ W1_edge, const float* __restrict__ att1_edge,
                        const float* __restrict__ W2_edge, const float* __restrict__ att2_edge,
                        const int*   __restrict__ ei){
    int tid = threadIdx.x;
    if (blockIdx.x == (NN + 255)/256){
        for (int i = tid; i < HID*6; i += 256){
            int k = i / 6, q = i % 6;
            float s = 0.f;
            const float* W   = (q < 3) ? W1_src   : W1_dst;
            const float* att = (q < 3) ? att1_src : att1_dst;
            int h = (q < 3) ? q : q - 3;
            #pragma unroll 8
            for (int c = 0; c < HID; c++)
                s += W[k*D1 + h*HID + c] * att[h*HID + c];
            g_watt[i] = s;
        }
        if (tid < 3){
            float s = 0.f;
            #pragma unroll 8
            for (int c = 0; c < HID; c++)
                s += W1_edge[tid*HID + c] * att1_edge[tid*HID + c];
            g_ce1[tid] = s;
        }
        if (tid == 254) g_ce2 = W2_edge[0] * att2_edge[0];
        if (tid == 255){
            int all0 = 1;
            for (int i = 0; i < 64; i++) if (ei[2*i+1] != 0) all0 = 0;
            g_is64 = all0;
        }
        return;
    }
    int idx = blockIdx.x * 256 + tid;
    if (idx < NN) g_deg[idx] = 0;
}

// ---------------- edges: decode + degree histogram ----------------
__global__ void k_edges(const void* eiv){
    int e = blockIdx.x * blockDim.x + threadIdx.x;
    if (e >= EE) return;
    int s, d;
    if (g_is64){
        const long long* p = (const long long*)eiv;
        s = (int)p[e]; d = (int)p[EE + e];
    } else {
        const int* p = (const int*)eiv;
        s = p[e]; d = p[EE + e];
    }
    g_src[e] = s; g_dst[e] = d;
    atomicAdd(&g_deg[d], 1);
}

// ---------------- single-block scan ----------------
__global__ void k_scan(){
    __shared__ int sh[1024];
    int tid = threadIdx.x;
    const int ITEMS = 49;     // 1024*49 >= NN
    int base = tid * ITEMS;
    int sum = 0;
    for (int i = 0; i < ITEMS; i++){ int idx = base + i; if (idx < NN) sum += g_deg[idx]; }
    sh[tid] = sum; __syncthreads();
    for (int off = 1; off < 1024; off <<= 1){
        int t = (tid >= off) ? sh[tid - off] : 0;
        __syncthreads();
        sh[tid] += t;
        __syncthreads();
    }
    int run = sh[tid] - sum;  // exclusive prefix
    for (int i = 0; i < ITEMS; i++){
        int idx = base + i;
        if (idx < NN){ g_rowptr[idx] = run; g_cursor[idx] = run; run += g_deg[idx]; }
    }
    if (tid == 1023) g_rowptr[NN] = sh[1023];
}

// ---------------- fused encoder + xs1 GEMM (fp16 out) + a_src/a_dst ----------------
// 192 threads = 24 col-octets x 8 node-quads; 32 nodes per block
__global__ void __launch_bounds__(192) k_xs(const float* __restrict__ x,
                                            const float* __restrict__ W1_src,
                                            const float* __restrict__ Wc, const float* __restrict__ bc,
                                            const float* __restrict__ Wt, const float* __restrict__ bt){
    __shared__ float A[HID][TN];     // A[k][n] : h values (rows 128B)
    __shared__ float sx[TN*5];
    __shared__ float sW[5*HID];
    int tid = threadIdx.x;
    int nb = blockIdx.x * TN;

    if (tid < 128) sW[tid] = Wc[tid];
    else if (tid < 192) sW[tid] = Wt[tid - 128];
    if (tid < 64) sW[192 + tid] = bc[tid];
    else if (tid < 128) sW[192 + tid] = bt[tid - 64];
    if (tid < TN*5){
        int gi = nb*5 + tid;
        sx[tid] = (gi < NN*5) ? x[gi] : 0.f;
    }
    __syncthreads();

    for (int i = tid; i < HID*TN; i += 192){
        int k = i >> 5, n = i & 31;
        float mask = sx[n*5+0], f0 = sx[n*5+1], f1 = sx[n*5+2], f2 = sx[n*5+3];
        float comm = f0*sW[k] + f1*sW[64+k] + sW[192+k];
        float toll = f2*sW[128+k] + sW[256+k];
        float v = comm*(1.f - mask) + toll*mask;
        A[k][n] = v > 0.f ? v : expm1f(v);
    }
    __syncthreads();

    int tx = tid % 24, ty = tid / 24;    // tx: 8-col group, ty: 4-node group
    const float4* A4 = (const float4*)A; // 8 float4 per 32-float row
    float4 acc[4][2];
    #pragma unroll
    for (int j = 0; j < 4; j++){ acc[j][0] = make_float4(0,0,0,0); acc[j][1] = make_float4(0,0,0,0); }

    #pragma unroll 4
    for (int k = 0; k < HID; k++){
        float4 wA = __ldg((const float4*)&W1_src[k*D1 + tx*8]);
        float4 wB = __ldg((const float4*)&W1_src[k*D1 + tx*8 + 4]);
        float4 a = A4[k*8 + ty];
        float av[4] = {a.x, a.y, a.z, a.w};
        #pragma unroll
        for (int j = 0; j < 4; j++){
            acc[j][0].x += av[j]*wA.x; acc[j][0].y += av[j]*wA.y;
            acc[j][0].z += av[j]*wA.z; acc[j][0].w += av[j]*wA.w;
            acc[j][1].x += av[j]*wB.x; acc[j][1].y += av[j]*wB.y;
            acc[j][1].z += av[j]*wB.z; acc[j][1].w += av[j]*wB.w;
        }
    }
    int n0 = nb + ty*4;
    #pragma unroll
    for (int j = 0; j < 4; j++){
        int nidx = n0 + j;
        if (nidx < NN){
            uint4 pk = make_uint4(f2_to_h2u(acc[j][0].x, acc[j][0].y),
                                  f2_to_h2u(acc[j][0].z, acc[j][0].w),
                                  f2_to_h2u(acc[j][1].x, acc[j][1].y),
                                  f2_to_h2u(acc[j][1].z, acc[j][1].w));
            *(uint4*)&g_xs1h[nidx*(D1/2) + tx*4] = pk;
        }
    }

    // a_src / a_dst: 32 nodes x 6 projections = 192 threads exactly
    {
        int n = tid / 6, q = tid % 6;
        if (nb + n < NN){
            float s = 0.f;
            #pragma unroll 8
            for (int k = 0; k < HID; k++)
                s += A[k][n] * g_watt[k*6 + q];
            if (q < 3) g_as1[(nb+n)*4 + q] = s;
            else       g_ad1[(nb+n)*4 + (q-3)] = s;
        }
    }
}

// ---------------- scatter: CSR + fused per-edge exp(logit) ----------------
__global__ void k_scatter(const float* __restrict__ edge_attr){
    int e = blockIdx.x * blockDim.x + threadIdx.x;
    if (e >= EE) return;
    int s = g_src[e], d = g_dst[e];
    float ea = __ldg(&edge_attr[e]);
    float4 as = *(const float4*)&g_as1[s*4];
    float4 ad = *(const float4*)&g_ad1[d*4];
    float w0 = __expf(lrelu(as.x + ad.x + ea*g_ce1[0]));
    float w1 = __expf(lrelu(as.y + ad.y + ea*g_ce1[1]));
    float w2 = __expf(lrelu(as.z + ad.z + ea*g_ce1[2]));
    int p = atomicAdd(&g_cursor[d], 1);
    g_er[p] = make_float4(w0, w1, w2, __int_as_float(s));
    g_esrc[p] = s;
    g_eea[p] = ea * g_ce2;
}

// ---------------- layer-1 warp-per-node aggregation (register/shuffle staging) ----------------
__global__ void __launch_bounds__(256) k_l1(const float* __restrict__ b1,
                                            const float* __restrict__ W2_src,
                                            const float* __restrict__ W2_dst,
                                            const float* __restrict__ att2_src,
                                            const float* __restrict__ att2_dst){
    int wslot = threadIdx.x >> 5, lane = threadIdx.x & 31;
    int n = blockIdx.x * 8 + wslot;
    if (n >= NN) return;                 // warp-uniform
    int start = g_rowptr[n], deg = g_rowptr[n+1] - start;

    float2 acc0 = {0,0}, acc1 = {0,0}, acc2 = {0,0};
    float den0=0.f, den1=0.f, den2=0.f;
    for (int base = 0; base < deg; base += 32){
        int cn = min(32, deg - base);
        float4 er = make_float4(0.f, 0.f, 0.f, 0.f);
        if (lane < cn) er = __ldg(&g_er[start + base + lane]);
        den0 += er.x; den1 += er.y; den2 += er.z;
        #pragma unroll 2
        for (int i = 0; i < cn; i++){
            float wx = __shfl_sync(0xffffffffu, er.x, i);
            float wy = __shfl_sync(0xffffffffu, er.y, i);
            float wz = __shfl_sync(0xffffffffu, er.z, i);
            int   s  = __shfl_sync(0xffffffffu, __float_as_int(er.w), i);
            const __half2* row = &g_xs1h[s * (D1/2)];
            float2 v0 = __half22float2(__ldg(&row[lane      ]));
            float2 v1 = __half22float2(__ldg(&row[lane + 32 ]));
            float2 v2 = __half22float2(__ldg(&row[lane + 64 ]));
            acc0.x += v0.x*wx; acc0.y += v0.y*wx;
            acc1.x += v1.x*wy; acc1.y += v1.y*wy;
            acc2.x += v2.x*wz; acc2.y += v2.y*wz;
        }
    }
    #pragma unroll
    for (int o = 16; o > 0; o >>= 1){
        den0 += __shfl_xor_sync(0xffffffffu, den0, o);
        den1 += __shfl_xor_sync(0xffffffffu, den1, o);
        den2 += __shfl_xor_sync(0xffffffffu, den2, o);
    }
    float id0 = 1.f/(den0 + 1e-16f), id1 = 1.f/(den1 + 1e-16f), id2 = 1.f/(den2 + 1e-16f);

    // epilogue: bias+ELU then fused layer-2 projections (channels 64h+2*lane+{0,1})
    float vs = 0.f, vd = 0.f;
    float2 accs[3] = { make_float2(acc0.x*id0, acc0.y*id0),
                       make_float2(acc1.x*id1, acc1.y*id1),
                       make_float2(acc2.x*id2, acc2.y*id2) };
    #pragma unroll
    for (int h = 0; h < 3; h++){
        int ci = h*32 + lane;
        float2 bb = __ldg(&((const float2*)b1)[ci]);
        float2 ws = __ldg(&((const float2*)W2_src)[ci]);
        float2 wdv = __ldg(&((const float2*)W2_dst)[ci]);
        float o0 = accs[h].x + bb.x, o1 = accs[h].y + bb.y;
        float h0 = o0 > 0.f ? o0 : expm1f(o0);
        float h1 = o1 > 0.f ? o1 : expm1f(o1);
        vs += h0*ws.x + h1*ws.y;
        vd += h0*wdv.x + h1*wdv.y;
    }
    #pragma unroll
    for (int o = 16; o > 0; o >>= 1){
        vs += __shfl_xor_sync(0xffffffffu, vs, o);
        vd += __shfl_xor_sync(0xffffffffu, vd, o);
    }
    if (lane == 0){
        g_a2sx[n] = make_float2(vs * att2_src[0], vs);
        g_a2d[n]  = vd * att2_dst[0];
    }
}

// ---------------- layer-2 single-pass warp-per-node aggregation + final mask ----------------
__global__ void __launch_bounds__(256) k_l2(const float* __restrict__ x,
                                            const float* __restrict__ b2,
                                            float* __restrict__ out){
    int wslot = threadIdx.x >> 5, lane = threadIdx.x & 31;
    int n = blockIdx.x * 8 + wslot;
    if (n >= NN) return;
    int start = g_rowptr[n], deg = g_rowptr[n+1] - start;
    float ad = g_a2d[n];

    float num = 0.f, den = 0.f;
    for (int i = lane; i < deg; i += 32){
        int s = __ldg(&g_esrc[start + i]);
        float eace = __ldg(&g_eea[start + i]);
        float2 a2 = __ldg(&g_a2sx[s]);          // {a2s, xs2}
        float r = lrelu(a2.x + ad + eace);
        float w = __expf(r);
        num += a2.y * w;
        den += w;
    }
    #pragma unroll
    for (int o = 16; o > 0; o >>= 1){
        num += __shfl_xor_sync(0xffffffffu, num, o);
        den += __shfl_xor_sync(0xffffffffu, den, o);
    }
    if (lane == 0){
        float v = num / (den + 1e-16f) + b2[0];
        out[n] = v * x[n*5 + 0];
    }
}

// ---------------- launch ----------------
extern "C" void kernel_launch(void* const* d_in, const int* in_sizes, int n_in,
                              void* d_out, int out_size){
    const float* x        = (const float*)d_in[0];
    const void*  ei       = d_in[1];
    const float* eattr    = (const float*)d_in[2];
    const float* W_comm   = (const float*)d_in[3];
    const float* b_comm   = (const float*)d_in[4];
    const float* W_toll   = (const float*)d_in[5];
    const float* b_toll   = (const float*)d_in[6];
    const float* W1_src   = (const float*)d_in[7];
    const float* W1_dst   = (const float*)d_in[8];
    const float* att1_src = (const float*)d_in[9];
    const float* att1_dst = (const float*)d_in[10];
    const float* W1_edge  = (const float*)d_in[11];
    const float* att1_edge= (const float*)d_in[12];
    const float* b1       = (const float*)d_in[13];
    const float* W2_src   = (const float*)d_in[14];
    const float* W2_dst   = (const float*)d_in[15];
    const float* att2_src = (const float*)d_in[16];
    const float* att2_dst = (const float*)d_in[17];
    const float* W2_edge  = (const float*)d_in[18];
    const float* att2_edge= (const float*)d_in[19];
    const float* b2       = (const float*)d_in[20];
    float* out = (float*)d_out;

    k_front<<<(NN + 255)/256 + 1, 256>>>(W1_src, att1_src, W1_dst, att1_dst,
                                         W1_edge, att1_edge, W2_edge, att2_edge,
                                         (const int*)ei);
    k_edges<<<(EE + 255)/256, 256>>>(ei);
    k_scan<<<1, 1024>>>();
    k_xs<<<(NN + TN - 1)/TN, 192>>>(x, W1_src, W_comm, b_comm, W_toll, b_toll);
    k_scatter<<<(EE + 255)/256, 256>>>(eattr);
    k_l1<<<(NN + 7)/8, 256>>>(b1, W2_src, W2_dst, att2_src, att2_dst);
    k_l2<<<(NN + 7)/8, 256>>>(x, b2, out);
}

// round 14
// speedup vs baseline: 1.1126x; 1.1126x over previous
#include <cuda_runtime.h>
#include <cuda_fp16.h>
#include <math.h>

#define NN 50000
#define EE 800000
#define HID 64
#define NH 3
#define D1 192   // NH*HID
#define TN 16    // nodes per k_xs block

// ---------------- scratch (device globals) ----------------
__device__ __half2 g_xs1h[NN*(D1/2)];  // h @ W1_src, fp16 (96 half2 per node)
__device__ float  g_as1[NN*4];     // per-node a_src (3 used, padded to float4)
__device__ float  g_ad1[NN*4];     // per-node a_dst
__device__ int    g_src[EE];
__device__ int    g_dst[EE];
__device__ int    g_deg[NN];
__device__ int    g_rowptr[NN+1];
__device__ int    g_cursor[NN];
__device__ float4 g_er[EE];        // per-edge {w0,w1,w2,src_bits} grouped by dst (w=exp(logit))
__device__ float2 g_e2[EE];        // per-edge {src_bits, ea*ce2} grouped by dst (for k_l2)
__device__ float2 g_a2sx[NN];      // {a2s, xs2}
__device__ float  g_a2d[NN];       // (h1 @ W2_dst) * att2_dst
__device__ float  g_watt[HID*6];   // [k*6+q]: q<3 -> fold(W1_src,att1_src), q>=3 -> fold(W1_dst,att1_dst)
__device__ float  g_ce1[NH];
__device__ float  g_ce2;
__device__ int    g_is64;

__device__ __forceinline__ float lrelu(float v){ return v > 0.f ? v : 0.2f*v; }

// bit-cast two floats -> packed __half2 -> uint
__device__ __forceinline__ unsigned int f2_to_h2u(float a, float b){
    __half2 h = __floats2half2_rn(a, b);
    union { __half2 h; unsigned int u; } cvt;
    cvt.h = h;
    return cvt.u;
}

// ---------------- front: zero deg + folds + dtype detect ----------------
__global__ void k_front(const float* __restrict__ W1_src, const float* __restrict__ att1_src,
                        const float* __restrict__ W1_dst, const float* __restrict__ att1_dst,
                        const float* __restrict__ W1_edge, const float* __restrict__ att1_edge,
                        const float* __restrict__ W2_edge, const float* __restrict__ att2_edge,
                        const int*   __restrict__ ei){
    int tid = threadIdx.x;
    if (blockIdx.x == (NN + 255)/256){
        for (int i = tid; i < HID*6; i += 256){
            int k = i / 6, q = i % 6;
            float s = 0.f;
            const float* W   = (q < 3) ? W1_src   : W1_dst;
            const float* att = (q < 3) ? att1_src : att1_dst;
            int h = (q < 3) ? q : q - 3;
            #pragma unroll 8
            for (int c = 0; c < HID; c++)
                s += W[k*D1 + h*HID + c] * att[h*HID + c];
            g_watt[i] = s;
        }
        if (tid < 3){
            float s = 0.f;
            #pragma unroll 8
            for (int c = 0; c < HID; c++)
                s += W1_edge[tid*HID + c] * att1_edge[tid*HID + c];
            g_ce1[tid] = s;
        }
        if (tid == 254) g_ce2 = W2_edge[0] * att2_edge[0];
        if (tid == 255){
            int all0 = 1;
            for (int i = 0; i < 64; i++) if (ei[2*i+1] != 0) all0 = 0;
            g_is64 = all0;
        }
        return;
    }
    int idx = blockIdx.x * 256 + tid;
    if (idx < NN) g_deg[idx] = 0;
}

// ---------------- edges: decode + degree histogram ----------------
__global__ void k_edges(const void* eiv){
    int e = blockIdx.x * blockDim.x + threadIdx.x;
    if (e >= EE) return;
    int s, d;
    if (g_is64){
        const long long* p = (const long long*)eiv;
        s = (int)p[e]; d = (int)p[EE + e];
    } else {
        const int* p = (const int*)eiv;
        s = p[e]; d = p[EE + e];
    }
    g_src[e] = s; g_dst[e] = d;
    atomicAdd(&g_deg[d], 1);
}

// ---------------- single-block scan ----------------
__global__ void k_scan(){
    __shared__ int sh[1024];
    int tid = threadIdx.x;
    const int ITEMS = 49;     // 1024*49 >= NN
    int base = tid * ITEMS;
    int sum = 0;
    for (int i = 0; i < ITEMS; i++){ int idx = base + i; if (idx < NN) sum += g_deg[idx]; }
    sh[tid] = sum; __syncthreads();
    for (int off = 1; off < 1024; off <<= 1){
        int t = (tid >= off) ? sh[tid - off] : 0;
        __syncthreads();
        sh[tid] += t;
        __syncthreads();
    }
    int run = sh[tid] - sum;  // exclusive prefix
    for (int i = 0; i < ITEMS; i++){
        int idx = base + i;
        if (idx < NN){ g_rowptr[idx] = run; g_cursor[idx] = run; run += g_deg[idx]; }
    }
    if (tid == 1023) g_rowptr[NN] = sh[1023];
}

// ---------------- fused encoder + xs1 GEMM (fp16 out) + a_src/a_dst ----------------
__global__ void __launch_bounds__(192) k_xs(const float* __restrict__ x,
                                            const float* __restrict__ W1_src,
                                            const float* __restrict__ Wc, const float* __restrict__ bc,
                                            const float* __restrict__ Wt, const float* __restrict__ bt){
    __shared__ float A[HID][TN];     // A[k][n] : h values
    __shared__ float sx[TN*5];
    __shared__ float sW[5*HID];
    int tid = threadIdx.x;
    int nb = blockIdx.x * TN;

    if (tid < 128) sW[tid] = Wc[tid];
    else if (tid < 192) sW[tid] = Wt[tid - 128];
    if (tid < 64) sW[192 + tid] = bc[tid];
    else if (tid < 128) sW[192 + tid] = bt[tid - 64];
    if (tid < TN*5) sx[tid] = x[nb*5 + tid];
    __syncthreads();

    for (int i = tid; i < HID*TN; i += 192){
        int k = i / TN, n = i % TN;
        float mask = sx[n*5+0], f0 = sx[n*5+1], f1 = sx[n*5+2], f2 = sx[n*5+3];
        float comm = f0*sW[k] + f1*sW[64+k] + sW[192+k];
        float toll = f2*sW[128+k] + sW[256+k];
        float v = comm*(1.f - mask) + toll*mask;
        A[k][n] = v > 0.f ? v : expm1f(v);
    }
    __syncthreads();

    int tx = tid % 48, ty = tid / 48;
    const float4* A4 = (const float4*)A;
    const float4* wp = (const float4*)&W1_src[tx*4];   // stride 48 float4 per k
    const float4* ap = &A4[ty];                        // stride 4 float4 per k
    float4 c0 = {0,0,0,0}, c1 = {0,0,0,0}, c2 = {0,0,0,0}, c3 = {0,0,0,0};
    #pragma unroll 4
    for (int k = 0; k < HID; k++){
        float4 w = __ldg(wp); wp += D1/4;
        float4 a = *ap; ap += 4;
        c0.x += a.x*w.x; c0.y += a.x*w.y; c0.z += a.x*w.z; c0.w += a.x*w.w;
        c1.x += a.y*w.x; c1.y += a.y*w.y; c1.z += a.y*w.z; c1.w += a.y*w.w;
        c2.x += a.z*w.x; c2.y += a.z*w.y; c2.z += a.z*w.z; c2.w += a.z*w.w;
        c3.x += a.w*w.x; c3.y += a.w*w.y; c3.z += a.w*w.z; c3.w += a.w*w.w;
    }
    int n0 = nb + ty*4;
    *(uint2*)&g_xs1h[(n0+0)*(D1/2) + tx*2] = make_uint2(f2_to_h2u(c0.x,c0.y), f2_to_h2u(c0.z,c0.w));
    *(uint2*)&g_xs1h[(n0+1)*(D1/2) + tx*2] = make_uint2(f2_to_h2u(c1.x,c1.y), f2_to_h2u(c1.z,c1.w));
    *(uint2*)&g_xs1h[(n0+2)*(D1/2) + tx*2] = make_uint2(f2_to_h2u(c2.x,c2.y), f2_to_h2u(c2.z,c2.w));
    *(uint2*)&g_xs1h[(n0+3)*(D1/2) + tx*2] = make_uint2(f2_to_h2u(c3.x,c3.y), f2_to_h2u(c3.z,c3.w));

    if (tid < TN*6){
        int n = tid / 6, q = tid % 6;
        float s = 0.f;
        #pragma unroll 8
        for (int k = 0; k < HID; k++)
            s += A[k][n] * g_watt[k*6 + q];
        if (q < 3) g_as1[(nb+n)*4 + q] = s;
        else       g_ad1[(nb+n)*4 + (q-3)] = s;
    }
}

// ---------------- scatter: CSR + fused per-edge exp(logit) ----------------
__global__ void k_scatter(const float* __restrict__ edge_attr){
    int e = blockIdx.x * blockDim.x + threadIdx.x;
    if (e >= EE) return;
    int s = g_src[e], d = g_dst[e];
    float ea = __ldg(&edge_attr[e]);
    float4 as = *(const float4*)&g_as1[s*4];
    float4 ad = *(const float4*)&g_ad1[d*4];
    float w0 = __expf(lrelu(as.x + ad.x + ea*g_ce1[0]));
    float w1 = __expf(lrelu(as.y + ad.y + ea*g_ce1[1]));
    float w2 = __expf(lrelu(as.z + ad.z + ea*g_ce1[2]));
    int p = atomicAdd(&g_cursor[d], 1);
    g_er[p] = make_float4(w0, w1, w2, __int_as_float(s));
    g_e2[p] = make_float2(__int_as_float(s), ea * g_ce2);
}

// ---------------- layer-1 warp-per-node aggregation (single pass) ----------------
__global__ void __launch_bounds__(256) k_l1(const float* __restrict__ b1,
                                            const float* __restrict__ W2_src,
                                            const float* __restrict__ W2_dst,
                                            const float* __restrict__ att2_src,
                                            const float* __restrict__ att2_dst){
    __shared__ float4 s_w[8][32];
    int wslot = threadIdx.x >> 5, lane = threadIdx.x & 31;
    int n = blockIdx.x * 8 + wslot;
    if (n >= NN) return;                 // warp-uniform
    int start = g_rowptr[n], deg = g_rowptr[n+1] - start;

    float2 acc0 = {0,0}, acc1 = {0,0}, acc2 = {0,0};
    float den0=0.f, den1=0.f, den2=0.f;
    for (int base = 0; base < deg; base += 32){
        int cn = min(32, deg - base);
        if (lane < cn){
            float4 er = __ldg(&g_er[start + base + lane]);   // weights precomputed
            den0 += er.x; den1 += er.y; den2 += er.z;
            s_w[wslot][lane] = er;
        }
        __syncwarp();
        #pragma unroll 2
        for (int i = 0; i < cn; i++){
            float4 w = s_w[wslot][i];
            const __half2* row = &g_xs1h[__float_as_int(w.w) * (D1/2)];
            float2 v0 = __half22float2(__ldg(&row[lane      ]));  // head 0: ch 2*lane..
            float2 v1 = __half22float2(__ldg(&row[lane + 32 ]));  // head 1
            float2 v2 = __half22float2(__ldg(&row[lane + 64 ]));  // head 2
            acc0.x += v0.x*w.x; acc0.y += v0.y*w.x;
            acc1.x += v1.x*w.y; acc1.y += v1.y*w.y;
            acc2.x += v2.x*w.z; acc2.y += v2.y*w.z;
        }
        __syncwarp();
    }
    #pragma unroll
    for (int o = 16; o > 0; o >>= 1){
        den0 += __shfl_xor_sync(0xffffffffu, den0, o);
        den1 += __shfl_xor_sync(0xffffffffu, den1, o);
        den2 += __shfl_xor_sync(0xffffffffu, den2, o);
    }
    float id0 = 1.f/(den0 + 1e-16f), id1 = 1.f/(den1 + 1e-16f), id2 = 1.f/(den2 + 1e-16f);

    // epilogue: bias+ELU then fused layer-2 projections (channels 64h+2*lane+{0,1})
    float vs = 0.f, vd = 0.f;
    float2 accs[3] = { make_float2(acc0.x*id0, acc0.y*id0),
                       make_float2(acc1.x*id1, acc1.y*id1),
                       make_float2(acc2.x*id2, acc2.y*id2) };
    #pragma unroll
    for (int h = 0; h < 3; h++){
        int ci = h*32 + lane;
        float2 bb = __ldg(&((const float2*)b1)[ci]);
        float2 ws = __ldg(&((const float2*)W2_src)[ci]);
        float2 wdv = __ldg(&((const float2*)W2_dst)[ci]);
        float o0 = accs[h].x + bb.x, o1 = accs[h].y + bb.y;
        float h0 = o0 > 0.f ? o0 : expm1f(o0);
        float h1 = o1 > 0.f ? o1 : expm1f(o1);
        vs += h0*ws.x + h1*ws.y;
        vd += h0*wdv.x + h1*wdv.y;
    }
    #pragma unroll
    for (int o = 16; o > 0; o >>= 1){
        vs += __shfl_xor_sync(0xffffffffu, vs, o);
        vd += __shfl_xor_sync(0xffffffffu, vd, o);
    }
    if (lane == 0){
        g_a2sx[n] = make_float2(vs * att2_src[0], vs);
        g_a2d[n]  = vd * att2_dst[0];
    }
}

// ---------------- layer-2 single-pass warp-per-node aggregation + final mask ----------------
__global__ void __launch_bounds__(256) k_l2(const float* __restrict__ x,
                                            const float* __restrict__ b2,
                                            float* __restrict__ out){
    int wslot = threadIdx.x >> 5, lane = threadIdx.x & 31;
    int n = blockIdx.x * 8 + wslot;
    if (n >= NN) return;
    int start = g_rowptr[n], deg = g_rowptr[n+1] - start;
    float ad = g_a2d[n];

    float num = 0.f, den = 0.f;
    for (int i = lane; i < deg; i += 32){
        float2 e2 = __ldg(&g_e2[start + i]);    // {src_bits, ea*ce2}
        int s = __float_as_int(e2.x);
        float2 a2 = __ldg(&g_a2sx[s]);          // {a2s, xs2}
        float r = lrelu(a2.x + ad + e2.y);
        float w = __expf(r);
        num += a2.y * w;
        den += w;
    }
    #pragma unroll
    for (int o = 16; o > 0; o >>= 1){
        num += __shfl_xor_sync(0xffffffffu, num, o);
        den += __shfl_xor_sync(0xffffffffu, den, o);
    }
    if (lane == 0){
        float v = num / (den + 1e-16f) + b2[0];
        out[n] = v * x[n*5 + 0];
    }
}

// ---------------- launch ----------------
extern "C" void kernel_launch(void* const* d_in, const int* in_sizes, int n_in,
                              void* d_out, int out_size){
    const float* x        = (const float*)d_in[0];
    const void*  ei       = d_in[1];
    const float* eattr    = (const float*)d_in[2];
    const float* W_comm   = (const float*)d_in[3];
    const float* b_comm   = (const float*)d_in[4];
    const float* W_toll   = (const float*)d_in[5];
    const float* b_toll   = (const float*)d_in[6];
    const float* W1_src   = (const float*)d_in[7];
    const float* W1_dst   = (const float*)d_in[8];
    const float* att1_src = (const float*)d_in[9];
    const float* att1_dst = (const float*)d_in[10];
    const float* W1_edge  = (const float*)d_in[11];
    const float* att1_edge= (const float*)d_in[12];
    const float* b1       = (const float*)d_in[13];
    const float* W2_src   = (const float*)d_in[14];
    const float* W2_dst   = (const float*)d_in[15];
    const float* att2_src = (const float*)d_in[16];
    const float* att2_dst = (const float*)d_in[17];
    const float* W2_edge  = (const float*)d_in[18];
    const float* att2_edge= (const float*)d_in[19];
    const float* b2       = (const float*)d_in[20];
    float* out = (float*)d_out;

    k_front<<<(NN + 255)/256 + 1, 256>>>(W1_src, att1_src, W1_dst, att1_dst,
                                         W1_edge, att1_edge, W2_edge, att2_edge,
                                         (const int*)ei);
    k_edges<<<(EE + 255)/256, 256>>>(ei);
    k_scan<<<1, 1024>>>();
    k_xs<<<NN/TN, 192>>>(x, W1_src, W_comm, b_comm, W_toll, b_toll);
    k_scatter<<<(EE + 255)/256, 256>>>(eattr);
    k_l1<<<(NN + 7)/8, 256>>>(b1, W2_src, W2_dst, att2_src, att2_dst);
    k_l2<<<(NN + 7)/8, 256>>>(x, b2, out);
}